// round 17
// baseline (speedup 1.0000x reference)
#include <cuda_runtime.h>
#include <cuda_bf16.h>
#include <stdint.h>
#include <math.h>

#define NN_ 8192
#define FF_ 512
#define HH_ 256
#define RR_ 16
#define BB_ 32
#define LL_ 256
#define CC_ 7
#define EE_ 262144
#define NBASE_ 30
#define DD_ 768
#define RH_ 4096
#define NBIN (NN_ * RR_)
#define NW_ (RH_ + HH_)

typedef __nv_bfloat16 bf16;

// ---------------- scratch ----------------
__device__ __align__(16) float g_xw[(size_t)NN_ * RH_];
__device__ int   g_cnt[NBIN];
__device__ __align__(16) float g_cat[NN_ * FF_];      // [:,0:256]=agg2 [:,256:512]=out1
__device__ __align__(16) float g_scores[BB_ * LL_ * LL_];
__device__ __align__(16) float g_hidden[NN_ * HH_];
__device__ __align__(16) float g_logits[NN_ * CC_];

__device__ __align__(16) bf16 g_xh[NN_*FF_],   g_xl[NN_*FF_];
__device__ __align__(16) bf16 g_wth[NW_*FF_],  g_wtl[NW_*FF_];   // [Wcat^T ; root1^T]
__device__ __align__(16) bf16 g_w2th[HH_*FF_], g_w2tl[HH_*FF_];
__device__ __align__(16) bf16 g_wath[DD_*DD_], g_watl[DD_*DD_];
__device__ __align__(16) bf16 g_wlth[HH_*DD_], g_wltl[HH_*DD_];
__device__ __align__(16) bf16 g_cath[NN_*FF_], g_catl[NN_*FF_];
__device__ __align__(16) bf16 g_emoh[NN_*DD_], g_emol[NN_*DD_];
__device__ __align__(16) bf16 g_Xh[NN_*DD_],   g_Xl[NN_*DD_];
__device__ __align__(16) bf16 g_ah[BB_*LL_*LL_], g_al[BB_*LL_*LL_];
__device__ __align__(16) bf16 g_eTh[BB_*DD_*LL_], g_eTl[BB_*DD_*LL_];
__device__ __align__(16) bf16 g_atth[NN_*DD_], g_attl[NN_*DD_];

// ---------------- helpers ----------------
__device__ __forceinline__ uint32_t smem_u32(const void* p) {
    uint32_t a;
    asm("{ .reg .u64 t; cvta.to.shared.u64 t, %1; cvt.u32.u64 %0, t; }" : "=r"(a) : "l"(p));
    return a;
}
__device__ __forceinline__ void cpasync16(uint32_t dst, const void* src) {
    asm volatile("cp.async.cg.shared.global [%0], [%1], 16;" :: "r"(dst), "l"(src));
}
__device__ __forceinline__ void ldsm4(uint32_t* r, uint32_t addr) {
    asm volatile("ldmatrix.sync.aligned.m8n8.x4.shared.b16 {%0,%1,%2,%3}, [%4];"
        : "=r"(r[0]), "=r"(r[1]), "=r"(r[2]), "=r"(r[3]) : "r"(addr));
}
__device__ __forceinline__ void mma16816(float* c, const uint32_t* a, const uint32_t* b) {
    asm volatile("mma.sync.aligned.m16n8k16.row.col.f32.bf16.bf16.f32 "
        "{%0,%1,%2,%3},{%4,%5,%6,%7},{%8,%9},{%0,%1,%2,%3};"
        : "+f"(c[0]), "+f"(c[1]), "+f"(c[2]), "+f"(c[3])
        : "r"(a[0]), "r"(a[1]), "r"(a[2]), "r"(a[3]), "r"(b[0]), "r"(b[1]));
}
__device__ __forceinline__ void red4(float* p, float4 v) {
    asm volatile("red.global.add.v4.f32 [%0], {%1,%2,%3,%4};"
        :: "l"(p), "f"(v.x), "f"(v.y), "f"(v.z), "f"(v.w) : "memory");
}

// ---------------- HMMA GEMM (R16 proven: 2-stage, occ 2, warp tile 64x32) ----------------
#define TSTRIDE 80
#define TILE_B  10240
#define STAGE_B 40960
#define SMEM_BYTES (2 * STAGE_B)

template <int EPI, int HASB, int OSPL, int XWF>
__global__ void __launch_bounds__(256, 2) mmagemm_k(
    const bf16* __restrict__ Ah, const bf16* __restrict__ Al,
    const bf16* __restrict__ Bh, const bf16* __restrict__ Bl,
    float* __restrict__ C, bf16* __restrict__ Oh, bf16* __restrict__ Ol,
    const float* __restrict__ bias,
    int K, int ldc, long long sA, long long sB, long long sC)
{
    extern __shared__ __align__(16) char smem[];
    const int tid = threadIdx.x, lane = tid & 31, wid = tid >> 5;
    const int wm = (wid >> 2) * 64, wn = (wid & 3) * 32;
    const int bm = blockIdx.y << 7, bn = blockIdx.x << 7;
    Ah += blockIdx.z * sA;  Al += blockIdx.z * sA;
    Bh += blockIdx.z * sB;  Bl += blockIdx.z * sB;
    const uint32_t sbase = smem_u32(smem);
    const size_t rsk = (size_t)K * 2;

    float acc[4][4][4];
#pragma unroll
    for (int i = 0; i < 4; i++)
#pragma unroll
        for (int j = 0; j < 4; j++)
#pragma unroll
            for (int r = 0; r < 4; r++) acc[i][j][r] = 0.f;

    const char* pA0 = (const char*)Ah + (size_t)bm * rsk;
    const char* pA1 = (const char*)Al + (size_t)bm * rsk;
    const char* pB0 = (const char*)Bh + (size_t)bn * rsk;
    const char* pB1 = (const char*)Bl + (size_t)bn * rsk;

    auto issue = [&](int stage, int k0) {   // k0 in elements
        uint32_t d0 = sbase + stage * STAGE_B;
#pragma unroll
        for (int i = 0; i < 2; i++) {
            int task = tid + i * 256;
            int row = task >> 2, ch = task & 3;
            uint32_t doff = row * TSTRIDE + ch * 16;
            size_t goff = (size_t)row * rsk + (size_t)k0 * 2 + ch * 16;
            cpasync16(d0 + doff,              pA0 + goff);
            cpasync16(d0 + TILE_B + doff,     pA1 + goff);
            cpasync16(d0 + 2 * TILE_B + doff, pB0 + goff);
            cpasync16(d0 + 3 * TILE_B + doff, pB1 + goff);
        }
        asm volatile("cp.async.commit_group;" ::: "memory");
    };

    const int NK = K >> 5;
    issue(0, 0);
#pragma unroll 1
    for (int k = 0; k < NK; k++) {
        const int st = k & 1;
        if (k + 1 < NK) {
            issue(st ^ 1, (k + 1) << 5);
            asm volatile("cp.async.wait_group 1;" ::: "memory");
        } else {
            asm volatile("cp.async.wait_group 0;" ::: "memory");
        }
        __syncthreads();
        const uint32_t aB = sbase + st * STAGE_B;
        const int idx8 = lane & 7, q = lane >> 3;
#pragma unroll
        for (int ks = 0; ks < 2; ks++) {
            uint32_t arh[4][4], arl[4][4];
#pragma unroll
            for (int mf = 0; mf < 4; mf++) {
                uint32_t byte = (uint32_t)(wm + mf * 16 + (q & 1) * 8 + idx8) * TSTRIDE
                              + ks * 32 + (q >> 1) * 16;
                ldsm4(arh[mf], aB + byte);
                ldsm4(arl[mf], aB + TILE_B + byte);
            }
            uint32_t brh[4][2], brl[4][2];
#pragma unroll
            for (int nf2 = 0; nf2 < 2; nf2++) {
                uint32_t byte = (uint32_t)(wn + nf2 * 16 + (q >> 1) * 8 + idx8) * TSTRIDE
                              + ks * 32 + (q & 1) * 16;
                uint32_t r[4];
                ldsm4(r, aB + 2 * TILE_B + byte);
                brh[nf2 * 2][0] = r[0]; brh[nf2 * 2][1] = r[1];
                brh[nf2 * 2 + 1][0] = r[2]; brh[nf2 * 2 + 1][1] = r[3];
                ldsm4(r, aB + 3 * TILE_B + byte);
                brl[nf2 * 2][0] = r[0]; brl[nf2 * 2][1] = r[1];
                brl[nf2 * 2 + 1][0] = r[2]; brl[nf2 * 2 + 1][1] = r[3];
            }
#pragma unroll
            for (int mf = 0; mf < 4; mf++)
#pragma unroll
                for (int nf = 0; nf < 4; nf++) {
                    mma16816(acc[mf][nf], arh[mf], brh[nf]);
                    mma16816(acc[mf][nf], arh[mf], brl[nf]);
                    mma16816(acc[mf][nf], arl[mf], brh[nf]);
                }
        }
        __syncthreads();
    }

#pragma unroll
    for (int mf = 0; mf < 4; mf++) {
#pragma unroll
        for (int rh = 0; rh < 2; rh++) {
            int row = bm + wm + mf * 16 + (lane >> 2) + rh * 8;
#pragma unroll
            for (int nf = 0; nf < 4; nf++) {
                int col = bn + wn + nf * 8 + (lane & 3) * 2;
                float v0 = acc[mf][nf][rh * 2], v1 = acc[mf][nf][rh * 2 + 1];
                if (XWF) {
                    if (col < RH_) {
                        *(float2*)&g_xw[(long long)row * RH_ + col] = make_float2(v0, v1);
                    } else {
                        int cc = col - RH_;
                        v0 += bias[cc]; v1 += bias[cc + 1];
                        *(float2*)&g_cat[(size_t)row * FF_ + HH_ + cc] = make_float2(v0, v1);
                    }
                    continue;
                }
                if (HASB) { v0 += bias[col]; v1 += bias[col + 1]; }
                if (EPI == 1) { v0 = fmaxf(v0, 0.f); v1 = fmaxf(v1, 0.f); }
                if (EPI == 2) { v0 = tanhf(v0); v1 = tanhf(v1); }
                long long idx = (long long)row * ldc + col + blockIdx.z * sC;
                if (OSPL) {
                    bf16 h0 = __float2bfloat16(v0), h1 = __float2bfloat16(v1);
                    __nv_bfloat162 hp, lp;
                    hp.x = h0; hp.y = h1;
                    lp.x = __float2bfloat16(v0 - __bfloat162float(h0));
                    lp.y = __float2bfloat16(v1 - __bfloat162float(h1));
                    *(__nv_bfloat162*)&Oh[idx] = hp;
                    *(__nv_bfloat162*)&Ol[idx] = lp;
                } else {
                    *(float2*)&C[idx] = make_float2(v0, v1);
                }
            }
        }
    }
}

// ---------------- fused prep: zeros + xprep + all weight transposes + computeWt ----------------
__device__ __forceinline__ void tsplit_dev(
    const float* __restrict__ in, bf16* __restrict__ oh, bf16* __restrict__ ol,
    int ldi, int ldo, int bx, int by, int t, float (*sh)[33])
{
    int tx = t & 31, ty = t >> 5;
    int bxe = bx * 32, bye = by * 32;
#pragma unroll
    for (int j = 0; j < 4; ++j)
        sh[ty + j * 8][tx] = in[(size_t)(bye + ty + j * 8) * ldi + bxe + tx];
    __syncthreads();
#pragma unroll
    for (int j = 0; j < 4; ++j) {
        float v = sh[tx][ty + j * 8];
        size_t o = (size_t)(bxe + ty + j * 8) * ldo + bye + tx;
        bf16 h = __float2bfloat16(v);
        oh[o] = h;
        ol[o] = __float2bfloat16(v - __bfloat162float(h));
    }
}

#define PB0 512      // zcnt
#define PB1 8192     // zeroagg
#define PB2 16384    // xprep
#define PB3 128      // root1 tsplit (8,16)
#define PB4 64       // w_rel (8,8)
#define PB5 64       // w_root (8,8)
#define PB6 576      // w_att (24,24)
#define PB7 192      // w_lin (8,24)
#define PB8 128      // computeWt (16,8)
#define PREP_BLOCKS (PB0+PB1+PB2+PB3+PB4+PB5+PB6+PB7+PB8)

__global__ void __launch_bounds__(256) prep_k(
    const float* __restrict__ x, const float* __restrict__ basis,
    const float* __restrict__ comp, const float* __restrict__ root1,
    const float* __restrict__ w_rel, const float* __restrict__ w_root,
    const float* __restrict__ w_att, const float* __restrict__ w_lin)
{
    __shared__ float sh[32][33];
    __shared__ float cw[RR_ * NBASE_];
    int b = blockIdx.x, t = threadIdx.x;
    if (b < PB0) { int i = b * 256 + t; if (i < NBIN) g_cnt[i] = 0; return; }
    b -= PB0;
    if (b < PB1) {
        int i = b * 256 + t;
        g_cat[(size_t)(i >> 8) * FF_ + (i & 255)] = 0.f;
        return;
    }
    b -= PB1;
    if (b < PB2) {
        int i = b * 256 + t;
        float v = x[i];
        bf16 h = __float2bfloat16(v);
        bf16 l = __float2bfloat16(v - __bfloat162float(h));
        g_xh[i] = h;
        g_xl[i] = l;
        size_t eo = (size_t)(i >> 9) * DD_ + (i & 511);
        g_emoh[eo] = h;
        g_emol[eo] = l;
        return;
    }
    b -= PB2;
    if (b < PB3) { tsplit_dev(root1, g_wth + (size_t)RH_ * FF_, g_wtl + (size_t)RH_ * FF_, HH_, FF_, b & 7, b >> 3, t, sh); return; }
    b -= PB3;
    if (b < PB4) { tsplit_dev(w_rel, g_w2th, g_w2tl, HH_, FF_, b & 7, b >> 3, t, sh); return; }
    b -= PB4;
    if (b < PB5) { tsplit_dev(w_root, g_w2th + HH_, g_w2tl + HH_, HH_, FF_, b & 7, b >> 3, t, sh); return; }
    b -= PB5;
    if (b < PB6) { tsplit_dev(w_att, g_wath, g_watl, DD_, DD_, b % 24, b / 24, t, sh); return; }
    b -= PB6;
    if (b < PB7) { tsplit_dev(w_lin, g_wlth, g_wltl, HH_, DD_, b & 7, b >> 3, t, sh); return; }
    b -= PB7;
    // computeWt: bx=f-tile (0..15), by=h-tile (0..7)
    {
        int bx = b & 15, by = b >> 4;
        int f0 = bx * 32, h0 = by * 32;
        for (int i = t; i < RR_ * NBASE_; i += 256) cw[i] = comp[i];
        __syncthreads();
        int hl = t & 31, fq = t >> 5;
        float acc[RR_][4];
#pragma unroll
        for (int r = 0; r < RR_; r++)
#pragma unroll
            for (int q = 0; q < 4; q++) acc[r][q] = 0.f;
#pragma unroll 1
        for (int bb = 0; bb < NBASE_; bb++) {
            float bs[4];
#pragma unroll
            for (int q = 0; q < 4; q++)
                bs[q] = basis[((size_t)bb * FF_ + f0 + fq * 4 + q) * HH_ + h0 + hl];
#pragma unroll
            for (int r = 0; r < RR_; r++) {
                float c = cw[r * NBASE_ + bb];
#pragma unroll
                for (int q = 0; q < 4; q++) acc[r][q] = fmaf(c, bs[q], acc[r][q]);
            }
        }
#pragma unroll 1
        for (int r = 0; r < RR_; r++) {
            __syncthreads();
#pragma unroll
            for (int q = 0; q < 4; q++) sh[hl][fq * 4 + q] = acc[r][q];
            __syncthreads();
            int row = t >> 3, c4 = (t & 7) * 4;
            float v0 = sh[row][c4], v1 = sh[row][c4 + 1], v2 = sh[row][c4 + 2], v3 = sh[row][c4 + 3];
            size_t o = (size_t)(r * HH_ + h0 + row) * FF_ + f0 + c4;
            bf16 b0 = __float2bfloat16(v0), b1 = __float2bfloat16(v1);
            bf16 b2 = __float2bfloat16(v2), b3 = __float2bfloat16(v3);
            __nv_bfloat162 hA, hB, lA, lB;
            hA.x = b0; hA.y = b1; hB.x = b2; hB.y = b3;
            lA.x = __float2bfloat16(v0 - __bfloat162float(b0));
            lA.y = __float2bfloat16(v1 - __bfloat162float(b1));
            lB.x = __float2bfloat16(v2 - __bfloat162float(b2));
            lB.y = __float2bfloat16(v3 - __bfloat162float(b3));
            *(__nv_bfloat162*)&g_wth[o] = hA; *(__nv_bfloat162*)&g_wth[o + 2] = hB;
            *(__nv_bfloat162*)&g_wtl[o] = lA; *(__nv_bfloat162*)&g_wtl[o + 2] = lB;
        }
    }
}

// ---------------- counting + scatter ----------------
__global__ void count_k(const int* __restrict__ ei, const int* __restrict__ et) {
    int e = blockIdx.x * 256 + threadIdx.x;
    if (e < EE_) atomicAdd(&g_cnt[ei[EE_ + e] * RR_ + et[e]], 1);
}
__global__ void scatter_msg_k(const int* __restrict__ ei, const int* __restrict__ et) {
    int e = blockIdx.x * 8 + (threadIdx.x >> 5);
    int lane = threadIdx.x & 31;
    if (e >= EE_) return;
    int s = ei[e], d = ei[EE_ + e], r = et[e];
    float inv = 1.0f / (float)max(g_cnt[d * RR_ + r], 1);
    const float4* p = (const float4*)(g_xw + (size_t)s * RH_ + r * HH_);
    float* o = g_cat + (size_t)d * FF_ + HH_;
#pragma unroll
    for (int i = 0; i < 2; ++i) {
        float4 v = p[lane + i * 32];
        v.x *= inv; v.y *= inv; v.z *= inv; v.w *= inv;
        red4(o + (lane + i * 32) * 4, v);
    }
}
__global__ void scatter_agg2_k(const int* __restrict__ ei) {
    int e = blockIdx.x * 8 + (threadIdx.x >> 5);
    int lane = threadIdx.x & 31;
    if (e >= EE_) return;
    int s = ei[e], d = ei[EE_ + e];
    const float4* p = (const float4*)(g_cat + (size_t)s * FF_ + HH_);
    float* o = g_cat + (size_t)d * FF_;
#pragma unroll
    for (int i = 0; i < 2; ++i) {
        float4 v = p[lane + i * 32];
        red4(o + (lane + i * 32) * 4, v);
    }
}

// ---------------- misc ----------------
__global__ void split_k(const float* __restrict__ in, bf16* __restrict__ oh, bf16* __restrict__ ol, int n) {
    int i = blockIdx.x * 256 + threadIdx.x;
    if (i >= n) return;
    float v = in[i];
    bf16 h = __float2bfloat16(v);
    oh[i] = h;
    ol[i] = __float2bfloat16(v - __bfloat162float(h));
}
// both emotions transposes in one launch: z<BB -> hi, else lo
__global__ void tspbf2_k() {
    __shared__ bf16 t[32][33];
    int z = blockIdx.z;
    const bf16* pin = (z < BB_ ? g_emoh : g_emol) + (size_t)(z % BB_) * LL_ * DD_;
    bf16* pout = (z < BB_ ? g_eTh : g_eTl) + (size_t)(z % BB_) * DD_ * LL_;
    int bx = blockIdx.x * 32, by = blockIdx.y * 32;
    int tx = threadIdx.x, ty = threadIdx.y;
#pragma unroll
    for (int j = 0; j < 4; ++j)
        t[ty + j * 8][tx] = pin[(size_t)(by + ty + j * 8) * DD_ + bx + tx];
    __syncthreads();
#pragma unroll
    for (int j = 0; j < 4; ++j)
        pout[(size_t)(bx + ty + j * 8) * LL_ + by + tx] = t[tx][ty + j * 8];
}
__global__ void softmax_k() {
    const float* row = g_scores + (size_t)blockIdx.x * LL_;
    int t = threadIdx.x;
    int lane = t & 31, w = t >> 5;
    __shared__ float red[8];
    float v = row[t];
    float m = v;
#pragma unroll
    for (int o = 16; o > 0; o >>= 1) m = fmaxf(m, __shfl_xor_sync(0xffffffffu, m, o));
    if (lane == 0) red[w] = m;
    __syncthreads();
    m = red[0];
#pragma unroll
    for (int i = 1; i < 8; i++) m = fmaxf(m, red[i]);
    float e = expf(v - m);
    float s = e;
#pragma unroll
    for (int o = 16; o > 0; o >>= 1) s += __shfl_xor_sync(0xffffffffu, s, o);
    __syncthreads();
    if (lane == 0) red[w] = s;
    __syncthreads();
    s = 0.f;
#pragma unroll
    for (int i = 0; i < 8; i++) s += red[i];
    float a = e / s;
    bf16 hh = __float2bfloat16(a);
    size_t o = (size_t)blockIdx.x * LL_ + t;
    g_ah[o] = hh;
    g_al[o] = __float2bfloat16(a - __bfloat162float(hh));
}
__global__ void logits_k(const float* __restrict__ wfc, const float* __restrict__ bfc) {
    __shared__ float sw[HH_ * CC_];
    for (int i = threadIdx.x; i < HH_ * CC_; i += 256) sw[i] = wfc[i];
    __syncthreads();
    int n = blockIdx.x * 8 + (threadIdx.x >> 5);
    int lane = threadIdx.x & 31;
    const float* h = g_hidden + (size_t)n * HH_;
    float a[CC_];
#pragma unroll
    for (int c = 0; c < CC_; c++) a[c] = 0.f;
    for (int k = lane; k < HH_; k += 32) {
        float hv = h[k];
#pragma unroll
        for (int c = 0; c < CC_; c++) a[c] = fmaf(hv, sw[k * CC_ + c], a[c]);
    }
#pragma unroll
    for (int c = 0; c < CC_; c++)
#pragma unroll
        for (int o = 16; o > 0; o >>= 1) a[c] += __shfl_xor_sync(0xffffffffu, a[c], o);
    if (lane == 0)
#pragma unroll
        for (int c = 0; c < CC_; c++) g_logits[(size_t)n * CC_ + c] = a[c] + bfc[c];
}
__global__ void logsoftmax_k(float* __restrict__ out) {
    int u = blockIdx.x * 256 + threadIdx.x;
    if (u >= LL_ * CC_) return;
    int t = u / CC_, c = u % CC_;
    float vals[BB_];
    float m = -1e30f;
#pragma unroll
    for (int b = 0; b < BB_; b++) {
        vals[b] = g_logits[((size_t)(b * LL_ + t)) * CC_ + c];
        m = fmaxf(m, vals[b]);
    }
    float s = 0.f;
#pragma unroll
    for (int b = 0; b < BB_; b++) s += expf(vals[b] - m);
    float lse = m + logf(s);
#pragma unroll
    for (int b = 0; b < BB_; b++) out[((size_t)t * BB_ + b) * CC_ + c] = vals[b] - lse;
}

// ---------------- host ----------------
extern "C" void kernel_launch(void* const* d_in, const int* in_sizes, int n_in,
                              void* d_out, int out_size)
{
    const float* x      = (const float*)d_in[0];
    const int*   ei     = (const int*)  d_in[1];
    const int*   et     = (const int*)  d_in[3];
    const float* basis  = (const float*)d_in[8];
    const float* comp   = (const float*)d_in[9];
    const float* root1  = (const float*)d_in[10];
    const float* bias1  = (const float*)d_in[11];
    const float* w_rel  = (const float*)d_in[12];
    const float* b_rel  = (const float*)d_in[13];
    const float* w_root = (const float*)d_in[14];
    const float* w_att  = (const float*)d_in[15];
    const float* b_att  = (const float*)d_in[16];
    const float* w_lin  = (const float*)d_in[17];
    const float* b_lin  = (const float*)d_in[18];
    const float* w_fc   = (const float*)d_in[19];
    const float* b_fc   = (const float*)d_in[20];
    float* out = (float*)d_out;

    float *pxw, *pcat, *pscores, *phid;
    bf16 *pxh, *pxl, *pwth, *pwtl, *pw2h, *pw2l, *pwah, *pwal,
         *pwlh, *pwll, *pch, *pcl, *peh, *pel, *pXh, *pXl, *pah, *pal,
         *peTh, *peTl, *path, *patl;
    cudaGetSymbolAddress((void**)&pxw, g_xw);
    cudaGetSymbolAddress((void**)&pcat, g_cat);
    cudaGetSymbolAddress((void**)&pscores, g_scores);
    cudaGetSymbolAddress((void**)&phid, g_hidden);
    cudaGetSymbolAddress((void**)&pxh, g_xh);   cudaGetSymbolAddress((void**)&pxl, g_xl);
    cudaGetSymbolAddress((void**)&pwth, g_wth); cudaGetSymbolAddress((void**)&pwtl, g_wtl);
    cudaGetSymbolAddress((void**)&pw2h, g_w2th); cudaGetSymbolAddress((void**)&pw2l, g_w2tl);
    cudaGetSymbolAddress((void**)&pwah, g_wath); cudaGetSymbolAddress((void**)&pwal, g_watl);
    cudaGetSymbolAddress((void**)&pwlh, g_wlth); cudaGetSymbolAddress((void**)&pwll, g_wltl);
    cudaGetSymbolAddress((void**)&pch, g_cath);  cudaGetSymbolAddress((void**)&pcl, g_catl);
    cudaGetSymbolAddress((void**)&peh, g_emoh);  cudaGetSymbolAddress((void**)&pel, g_emol);
    cudaGetSymbolAddress((void**)&pXh, g_Xh);    cudaGetSymbolAddress((void**)&pXl, g_Xl);
    cudaGetSymbolAddress((void**)&pah, g_ah);    cudaGetSymbolAddress((void**)&pal, g_al);
    cudaGetSymbolAddress((void**)&peTh, g_eTh);  cudaGetSymbolAddress((void**)&peTl, g_eTl);
    cudaGetSymbolAddress((void**)&path, g_atth); cudaGetSymbolAddress((void**)&patl, g_attl);

    cudaFuncSetAttribute(mmagemm_k<0,0,0,1>, cudaFuncAttributeMaxDynamicSharedMemorySize, SMEM_BYTES);
    cudaFuncSetAttribute(mmagemm_k<0,1,1,0>, cudaFuncAttributeMaxDynamicSharedMemorySize, SMEM_BYTES);
    cudaFuncSetAttribute(mmagemm_k<2,0,0,0>, cudaFuncAttributeMaxDynamicSharedMemorySize, SMEM_BYTES);
    cudaFuncSetAttribute(mmagemm_k<0,0,1,0>, cudaFuncAttributeMaxDynamicSharedMemorySize, SMEM_BYTES);
    cudaFuncSetAttribute(mmagemm_k<1,1,0,0>, cudaFuncAttributeMaxDynamicSharedMemorySize, SMEM_BYTES);

    // fused prep (zeros + xprep + all weight transposes + computeWt), then counts
    prep_k<<<PREP_BLOCKS, 256>>>(x, basis, comp, root1, w_rel, w_root, w_att, w_lin);
    count_k<<<EE_ / 256, 256>>>(ei, et);

    // fused: xw = x @ Wcat  AND  out1 base = x @ root1 + bias1
    mmagemm_k<0,0,0,1><<<dim3(NW_ / 128, 64), 256, SMEM_BYTES>>>(
        pxh, pxl, pwth, pwtl, pxw, nullptr, nullptr, bias1, FF_, RH_, 0, 0, 0);
    // atomic scatters
    scatter_msg_k<<<EE_ / 8, 256>>>(ei, et);
    scatter_agg2_k<<<EE_ / 8, 256>>>(ei);
    // split cat; out2 = [agg2|out1] @ [w_rel;w_root] + b_rel -> emotions[:,512:768]
    split_k<<<NN_ * FF_ / 256, 256>>>(pcat, pch, pcl, NN_ * FF_);
    mmagemm_k<0,1,1,0><<<dim3(2, 64), 256, SMEM_BYTES>>>(
        pch, pcl, pw2h, pw2l, nullptr, peh + FF_, pel + FF_, b_rel, FF_, DD_, 0, 0, 0);
    // X = emotions @ w_att + b_att (bf16 split out)
    mmagemm_k<0,1,1,0><<<dim3(6, 64), 256, SMEM_BYTES>>>(
        peh, pel, pwah, pwal, nullptr, pXh, pXl, b_att, DD_, DD_, 0, 0, 0);
    // scores = tanh(X_b @ emotions_b^T)
    mmagemm_k<2,0,0,0><<<dim3(2, 2, BB_), 256, SMEM_BYTES>>>(
        pXh, pXl, peh, pel, pscores, nullptr, nullptr, nullptr, DD_, LL_,
        (long long)LL_ * DD_, (long long)LL_ * DD_, (long long)LL_ * LL_);
    softmax_k<<<BB_ * LL_, LL_>>>();
    // emotions^T per batch (hi+lo in one launch)
    tspbf2_k<<<dim3(24, 8, 2 * BB_), dim3(32, 8)>>>();
    // att = a_b @ emotions_b (bf16 split out)
    mmagemm_k<0,0,1,0><<<dim3(6, 2, BB_), 256, SMEM_BYTES>>>(
        pah, pal, peTh, peTl, nullptr, path, patl, nullptr, LL_, DD_,
        (long long)LL_ * LL_, (long long)DD_ * LL_, (long long)LL_ * DD_);
    // hidden = relu(att @ w_lin + b_lin)
    mmagemm_k<1,1,0,0><<<dim3(2, 64), 256, SMEM_BYTES>>>(
        path, patl, pwlh, pwll, phid, nullptr, nullptr, b_lin, DD_, HH_, 0, 0, 0);
    // logits + log_softmax
    logits_k<<<NN_ / 8, 256>>>(w_fc, b_fc);
    logsoftmax_k<<<(LL_ * CC_ + 255) / 256, 256>>>(out);
}